// round 12
// baseline (speedup 1.0000x reference)
#include <cuda_runtime.h>
#include <cuda_fp16.h>
#include <math.h>
#include <stdint.h>

#define H    768
#define F    3072
#define E    8
#define NTOK 1024
#define CAP  1024
#define ROWS (E*CAP)
#define NSPLIT 3
#define KSPL (F / NSPLIT)   // 1024

#define NSTG 3
// smem stage sizes (bytes)
#define ASTG 10240          // 128 rows x 80B (16 words used + 4 pad)
#define BSTG 4608           // 32 k-rows x 144B (64 halfs + 8 pad)
#define SB_B (NSTG*ASTG)
#define SMEM_BYTES (NSTG*(ASTG+BSTG))   // 44544

// ---- scratch (static device globals; no runtime allocation) ----
__device__ int      g_cnt[E];
__device__ int      g_tok[ROWS];
__device__ float    g_rw[ROWS];
__device__ int      g_slot_row[NTOK*2];
__device__ uint32_t g_xh[NTOK*(H/2)];            // x packed half2 along k
__device__ uint32_t g_hh[(size_t)ROWS*(F/2)];    // gelu(x@w1) packed half2 along k
__device__ __half   g_w1h[(size_t)E*H*F];        // w1 plain half [e][k][n]
__device__ __half   g_w2h[(size_t)E*F*H];        // w2 plain half [e][k][n]
__device__ float    g_ys[NSPLIT][(size_t)ROWS * H];

// ---------------------------------------------------------------
__device__ __forceinline__ uint32_t pack_h2(float a, float b) {
    __half2 h = __floats2half2_rn(a, b);
    return *(uint32_t*)&h;
}

__global__ void zero_cnt_kernel() {
    if (threadIdx.x < E) g_cnt[threadIdx.x] = 0;
}

// linear fp32 -> fp16 stream for both weights (layout preserved)
__global__ void convert_w_kernel(const float* __restrict__ w1,
                                 const float* __restrict__ w2) {
    size_t i = (size_t)blockIdx.x * blockDim.x + threadIdx.x;   // 8 elems each
    const size_t n1 = (size_t)E * H * F / 8;
    const size_t n2 = (size_t)E * F * H / 8;
    const float* src;
    __half* dst;
    size_t j;
    if (i < n1)           { src = w1; dst = g_w1h; j = i; }
    else if (i < n1 + n2) { src = w2; dst = g_w2h; j = i - n1; }
    else return;
    float4 a = ((const float4*)src)[2*j];
    float4 b = ((const float4*)src)[2*j+1];
    uint4 o;
    o.x = pack_h2(a.x, a.y); o.y = pack_h2(a.z, a.w);
    o.z = pack_h2(b.x, b.y); o.w = pack_h2(b.z, b.w);
    ((uint4*)dst)[j] = o;
}

// router + x fp16 packing fused (1 warp per token)
__global__ void router_kernel(const float* __restrict__ x,
                              const float* __restrict__ rw) {
    int warp = (blockIdx.x * blockDim.x + threadIdx.x) >> 5;
    int lane = threadIdx.x & 31;
    if (warp >= NTOK) return;
    const float* xr = x + warp * H;
    {
        const float4* src = (const float4*)xr;
        uint32_t* dst = g_xh + warp * (H/2);
#pragma unroll
        for (int i = lane; i < H / 4; i += 32) {
            float4 v = src[i];
            dst[2*i]   = pack_h2(v.x, v.y);
            dst[2*i+1] = pack_h2(v.z, v.w);
        }
    }
    float acc[E];
#pragma unroll
    for (int e = 0; e < E; e++) acc[e] = 0.f;
    for (int k = lane; k < H; k += 32) {
        float xv = xr[k];
        const float* r = rw + k * E;
#pragma unroll
        for (int e = 0; e < E; e++) acc[e] += xv * r[e];
    }
#pragma unroll
    for (int e = 0; e < E; e++) {
#pragma unroll
        for (int o = 16; o > 0; o >>= 1)
            acc[e] += __shfl_down_sync(0xffffffffu, acc[e], o);
    }
    if (lane == 0) {
        float b0 = -INFINITY, b1 = -INFINITY;
        int i0 = 0, i1 = 0;
#pragma unroll
        for (int e = 0; e < E; e++) {
            float v = acc[e];
            if (v > b0) { b1 = b0; i1 = i0; b0 = v; i0 = e; }
            else if (v > b1) { b1 = v; i1 = e; }
        }
        float s  = expf(b1 - b0);
        float w0 = 1.f / (1.f + s);
        float w1v = s / (1.f + s);
        int p0 = atomicAdd(&g_cnt[i0], 1);
        int r0 = i0 * CAP + p0;
        g_tok[r0] = warp; g_rw[r0] = w0; g_slot_row[warp * 2 + 0] = r0;
        int p1 = atomicAdd(&g_cnt[i1], 1);
        int r1 = i1 * CAP + p1;
        g_tok[r1] = warp; g_rw[r1] = w1v; g_slot_row[warp * 2 + 1] = r1;
    }
}

__device__ __forceinline__ float gelu_exact(float v) {
    return 0.5f * v * (1.0f + erff(v * 0.70710678118654752f));
}

__device__ __forceinline__ void mma_f16(float c[4],
                                        uint32_t a0, uint32_t a1, uint32_t a2, uint32_t a3,
                                        uint32_t b0, uint32_t b1) {
    asm volatile(
        "mma.sync.aligned.m16n8k16.row.col.f32.f16.f16.f32 "
        "{%0,%1,%2,%3},{%4,%5,%6,%7},{%8,%9},{%0,%1,%2,%3};"
        : "+f"(c[0]), "+f"(c[1]), "+f"(c[2]), "+f"(c[3])
        : "r"(a0), "r"(a1), "r"(a2), "r"(a3), "r"(b0), "r"(b1));
}
__device__ __forceinline__ void ldm_x4(uint32_t& r0, uint32_t& r1, uint32_t& r2, uint32_t& r3,
                                       uint32_t addr) {
    asm volatile("ldmatrix.sync.aligned.m8n8.x4.shared.b16 {%0,%1,%2,%3}, [%4];"
        : "=r"(r0), "=r"(r1), "=r"(r2), "=r"(r3) : "r"(addr));
}
__device__ __forceinline__ void ldm_x4t(uint32_t& r0, uint32_t& r1, uint32_t& r2, uint32_t& r3,
                                        uint32_t addr) {
    asm volatile("ldmatrix.sync.aligned.m8n8.x4.trans.shared.b16 {%0,%1,%2,%3}, [%4];"
        : "=r"(r0), "=r"(r1), "=r"(r2), "=r"(r3) : "r"(addr));
}

#define CP_ASYNC16(dst, src) \
    asm volatile("cp.async.cg.shared.global [%0], [%1], 16;" :: "r"(dst), "l"(src))
#define CP_COMMIT() asm volatile("cp.async.commit_group;")
#define CP_WAIT1()  asm volatile("cp.async.wait_group 1;")
#define CP_WAIT0()  asm volatile("cp.async.wait_group 0;")

// ---------------------------------------------------------------
// fp16 MMA FFN GEMM. Block tile 128x64, BK=32 f16, 8 warps (4m x 2n),
// warp tile 32x32 via m16n8k16. 3 stages, depth-2 prefetch, 1 barrier/iter.
// 3 blocks/SM (24 warps) via __launch_bounds__(256,3).
// MODE 0: g_hh = h2(gelu(g_xh[gather] @ w1h))  KSTR=768,  KLEN=768,  ND=3072
// MODE 1: g_ys[spl] = g_hh @ w2h[kslice]       KSTR=3072, KLEN=1024, ND=768
template<int KSTR, int KLEN, int ND, int MODE>
__global__ void __launch_bounds__(256, 3)
moe_mma_kernel() {
    int e, spl;
    if (MODE == 0) { e = blockIdx.z; spl = 0; }
    else           { e = blockIdx.z / NSPLIT; spl = blockIdx.z % NSPLIT; }
    const int cnt = g_cnt[e];
    const int m0  = blockIdx.y * 128;
    if (m0 >= cnt) return;
    const int n0   = blockIdx.x * 64;
    const int kbeg = spl * KLEN;

    extern __shared__ char smem[];
    const uint32_t sb = (uint32_t)__cvta_generic_to_shared(smem);

    const int t    = threadIdx.x;
    const int warp = t >> 5, lane = t & 31;
    const int wm = warp >> 1, wn = warp & 1;   // 4 m-warps x 2 n-warps
    const int g  = lane >> 2, tg = lane & 3;

    // ---- A loader: thread t -> row t>>1, word chunks (t&1)*8 + {0,4} ----
    const int am = t >> 1;
    const int ac = (t & 1) * 8;
    const uint32_t* arow;
    if (MODE == 0) {
        int tok = (m0 + am < cnt) ? g_tok[e * CAP + m0 + am] : 0;
        arow = g_xh + (size_t)tok * (KSTR/2);
    } else {
        int rr = e * CAP + ((m0 + am < cnt) ? m0 + am : 0);
        arow = g_hh + (size_t)rr * (KSTR/2) + (kbeg/2);
    }
    const uint32_t dA = sb + am * 80 + ac * 4;

    // ---- B loader: thread t -> k-row t>>3 (0..31), 16B at (t&7)*16 ----
    const int bk = t >> 3;
    const int bc = (t & 7) * 8;                 // half col
    const __half* wh = (MODE == 0) ? g_w1h : g_w2h;
    const __half* bptr = wh + ((size_t)e * KSTR + kbeg + bk) * ND + n0 + bc;
    const uint32_t dB = sb + SB_B + bk * 144 + bc * 2;

#define LOAD_STAGE(s, it2)                                             \
    do {                                                               \
        const uint32_t* asrc = arow + (size_t)(it2) * 16 + ac;         \
        CP_ASYNC16(dA + (s) * ASTG, asrc);                             \
        CP_ASYNC16(dA + (s) * ASTG + 16, asrc + 4);                    \
        const __half* bsrc = bptr + (size_t)(it2) * 32 * ND;           \
        CP_ASYNC16(dB + (s) * BSTG, bsrc);                             \
        CP_COMMIT();                                                   \
    } while (0)

    // ---- fragment ldmatrix base addresses ----
    const uint32_t aFrag = sb + (wm * 32 + (lane & 15)) * 80 + (lane >> 4) * 16;
    const uint32_t bFrag = sb + SB_B + (lane & 15) * 144 + wn * 64 + (lane >> 4) * 16;

    float acc[2][4][4];
#pragma unroll
    for (int mt = 0; mt < 2; mt++)
#pragma unroll
        for (int nt = 0; nt < 4; nt++)
#pragma unroll
            for (int i = 0; i < 4; i++) acc[mt][nt][i] = 0.f;

    const int NIT = KLEN / 32;
    LOAD_STAGE(0, 0);
    LOAD_STAGE(1, 1);

    int s = 0;
    for (int it = 0; it < NIT; it++) {
        if (it + 1 < NIT) CP_WAIT1(); else CP_WAIT0();
        __syncthreads();
        if (it + 2 < NIT) {
            int sn = s + 2; if (sn >= NSTG) sn -= NSTG;
            LOAD_STAGE(sn, it + 2);
        }

#pragma unroll
        for (int kk = 0; kk < 2; kk++) {
            uint32_t af[2][4];
#pragma unroll
            for (int mt = 0; mt < 2; mt++)
                ldm_x4(af[mt][0], af[mt][1], af[mt][2], af[mt][3],
                       aFrag + s * ASTG + kk * 32 + mt * 1280);
            uint32_t bf[2][4];
#pragma unroll
            for (int ntp = 0; ntp < 2; ntp++)
                ldm_x4t(bf[ntp][0], bf[ntp][1], bf[ntp][2], bf[ntp][3],
                        bFrag + s * BSTG + kk * 2304 + ntp * 32);
#pragma unroll
            for (int mt = 0; mt < 2; mt++)
#pragma unroll
                for (int nt = 0; nt < 4; nt++)
                    mma_f16(acc[mt][nt], af[mt][0], af[mt][1], af[mt][2], af[mt][3],
                            bf[nt >> 1][(nt & 1) * 2], bf[nt >> 1][(nt & 1) * 2 + 1]);
        }
        s++; if (s >= NSTG) s -= NSTG;
    }
#undef LOAD_STAGE

    // ---- epilogue ----
#pragma unroll
    for (int mt = 0; mt < 2; mt++) {
        int rloc0 = m0 + wm * 32 + mt * 16 + g;
        int rloc1 = rloc0 + 8;
#pragma unroll
        for (int nt = 0; nt < 4; nt++) {
            if (MODE == 0) {
                int pc = (n0 >> 1) + wn * 16 + nt * 4 + tg;   // packed half2 col
                if (rloc0 < cnt)
                    g_hh[(size_t)(e * CAP + rloc0) * (ND/2) + pc] =
                        pack_h2(gelu_exact(acc[mt][nt][0]), gelu_exact(acc[mt][nt][1]));
                if (rloc1 < cnt)
                    g_hh[(size_t)(e * CAP + rloc1) * (ND/2) + pc] =
                        pack_h2(gelu_exact(acc[mt][nt][2]), gelu_exact(acc[mt][nt][3]));
            } else {
                int cc = n0 + wn * 32 + nt * 8 + tg * 2;
                if (rloc0 < cnt) {
                    float* p = &g_ys[spl][(size_t)(e * CAP + rloc0) * ND + cc];
                    p[0] = acc[mt][nt][0];
                    p[1] = acc[mt][nt][1];
                }
                if (rloc1 < cnt) {
                    float* p = &g_ys[spl][(size_t)(e * CAP + rloc1) * ND + cc];
                    p[0] = acc[mt][nt][2];
                    p[1] = acc[mt][nt][3];
                }
            }
        }
    }
}

// ---------------------------------------------------------------
__global__ void combine_kernel(float* __restrict__ out) {
    int idx = blockIdx.x * blockDim.x + threadIdx.x;
    if (idx >= NTOK * H / 4) return;
    int elem = idx * 4;
    int n = elem / H;
    int h = elem % H;
    int r0 = g_slot_row[2 * n + 0];
    int r1 = g_slot_row[2 * n + 1];
    float gw0 = g_rw[r0], gw1 = g_rw[r1];

    float4 s0 = make_float4(0.f, 0.f, 0.f, 0.f);
    float4 s1 = make_float4(0.f, 0.f, 0.f, 0.f);
#pragma unroll
    for (int s = 0; s < NSPLIT; s++) {
        float4 a = *(const float4*)(&g_ys[s][0] + (size_t)r0 * H + h);
        float4 b = *(const float4*)(&g_ys[s][0] + (size_t)r1 * H + h);
        s0.x += a.x; s0.y += a.y; s0.z += a.z; s0.w += a.w;
        s1.x += b.x; s1.y += b.y; s1.z += b.z; s1.w += b.w;
    }
    float4 o;
    o.x = gw0 * s0.x + gw1 * s1.x;
    o.y = gw0 * s0.y + gw1 * s1.y;
    o.z = gw0 * s0.z + gw1 * s1.z;
    o.w = gw0 * s0.w + gw1 * s1.w;
    *(float4*)(out + elem) = o;
}

// ---------------------------------------------------------------
extern "C" void kernel_launch(void* const* d_in, const int* in_sizes, int n_in,
                              void* d_out, int out_size) {
    const float* x  = (const float*)d_in[0];
    const float* rw = (const float*)d_in[1];
    const float* w1 = (const float*)d_in[2];
    const float* w2 = (const float*)d_in[3];
    float* out = (float*)d_out;

    cudaFuncSetAttribute(moe_mma_kernel<H, H, F, 0>,
                         cudaFuncAttributeMaxDynamicSharedMemorySize, SMEM_BYTES);
    cudaFuncSetAttribute(moe_mma_kernel<F, KSPL, H, 1>,
                         cudaFuncAttributeMaxDynamicSharedMemorySize, SMEM_BYTES);

    zero_cnt_kernel<<<1, 32>>>();
    router_kernel<<<NTOK / 8, 256>>>(x, rw);

    size_t wtot = ((size_t)E * H * F + (size_t)E * F * H) / 8;
    convert_w_kernel<<<(unsigned)((wtot + 255) / 256), 256>>>(w1, w2);

    dim3 g1(F / 64, NTOK / 128, E);                  // (48, 8, 8)
    moe_mma_kernel<H, H, F, 0><<<g1, 256, SMEM_BYTES>>>();

    dim3 g2(H / 64, NTOK / 128, E * NSPLIT);         // (12, 8, 24)
    moe_mma_kernel<F, KSPL, H, 1><<<g2, 256, SMEM_BYTES>>>();

    combine_kernel<<<(NTOK * H / 4 + 255) / 256, 256>>>(out);
}

// round 14
// speedup vs baseline: 1.5042x; 1.5042x over previous
#include <cuda_runtime.h>
#include <cuda_fp16.h>
#include <math.h>
#include <stdint.h>

#define H    768
#define F    3072
#define E    8
#define NTOK 1024
#define CAP  1024
#define ROWS (E*CAP)
#define NSPLIT 3            // GEMM2 K-split
#define KSPL (F / NSPLIT)   // 1024
#define NSPL1 2             // GEMM1 K-split
#define KSPL1 (H / NSPL1)   // 384

#define NSTG 3
// smem stage sizes (bytes) — identical to R10
#define ASTG 10240          // 128 rows x 80B (16 words used + 4 pad)
#define BSTG 8704           // 32 k-rows x 272B (128 halfs + 8 pad)
#define SB_B (NSTG*ASTG)
#define SMEM_BYTES (NSTG*(ASTG+BSTG))   // 56832

// ---- scratch (static device globals; no runtime allocation) ----
__device__ int      g_cnt[E];
__device__ int      g_tok[ROWS];
__device__ float    g_rw[ROWS];
__device__ int      g_slot_row[NTOK*2];
__device__ uint32_t g_xh[NTOK*(H/2)];            // x packed half2 along k
__device__ uint32_t g_hh[(size_t)ROWS*(F/2)];    // gelu(x@w1) packed half2 along k
__device__ __half   g_w1h[(size_t)E*H*F];        // w1 plain half [e][k][n]
__device__ __half   g_w2h[(size_t)E*F*H];        // w2 plain half [e][k][n]
__device__ float    g_h1s[NSPL1][(size_t)ROWS * F];   // GEMM1 split partials (fp32)
__device__ float    g_ys[NSPLIT][(size_t)ROWS * H];

// ---------------------------------------------------------------
__device__ __forceinline__ uint32_t pack_h2(float a, float b) {
    __half2 h = __floats2half2_rn(a, b);
    return *(uint32_t*)&h;
}

__global__ void zero_cnt_kernel() {
    if (threadIdx.x < E) g_cnt[threadIdx.x] = 0;
}

// linear fp32 -> fp16 stream for both weights (layout preserved)
__global__ void convert_w_kernel(const float* __restrict__ w1,
                                 const float* __restrict__ w2) {
    size_t i = (size_t)blockIdx.x * blockDim.x + threadIdx.x;   // 8 elems each
    const size_t n1 = (size_t)E * H * F / 8;
    const size_t n2 = (size_t)E * F * H / 8;
    const float* src;
    __half* dst;
    size_t j;
    if (i < n1)           { src = w1; dst = g_w1h; j = i; }
    else if (i < n1 + n2) { src = w2; dst = g_w2h; j = i - n1; }
    else return;
    float4 a = ((const float4*)src)[2*j];
    float4 b = ((const float4*)src)[2*j+1];
    uint4 o;
    o.x = pack_h2(a.x, a.y); o.y = pack_h2(a.z, a.w);
    o.z = pack_h2(b.x, b.y); o.w = pack_h2(b.z, b.w);
    ((uint4*)dst)[j] = o;
}

// router + x fp16 packing fused (1 warp per token)
__global__ void router_kernel(const float* __restrict__ x,
                              const float* __restrict__ rw) {
    int warp = (blockIdx.x * blockDim.x + threadIdx.x) >> 5;
    int lane = threadIdx.x & 31;
    if (warp >= NTOK) return;
    const float* xr = x + warp * H;
    {
        const float4* src = (const float4*)xr;
        uint32_t* dst = g_xh + warp * (H/2);
#pragma unroll
        for (int i = lane; i < H / 4; i += 32) {
            float4 v = src[i];
            dst[2*i]   = pack_h2(v.x, v.y);
            dst[2*i+1] = pack_h2(v.z, v.w);
        }
    }
    float acc[E];
#pragma unroll
    for (int e = 0; e < E; e++) acc[e] = 0.f;
    for (int k = lane; k < H; k += 32) {
        float xv = xr[k];
        const float* r = rw + k * E;
#pragma unroll
        for (int e = 0; e < E; e++) acc[e] += xv * r[e];
    }
#pragma unroll
    for (int e = 0; e < E; e++) {
#pragma unroll
        for (int o = 16; o > 0; o >>= 1)
            acc[e] += __shfl_down_sync(0xffffffffu, acc[e], o);
    }
    if (lane == 0) {
        float b0 = -INFINITY, b1 = -INFINITY;
        int i0 = 0, i1 = 0;
#pragma unroll
        for (int e = 0; e < E; e++) {
            float v = acc[e];
            if (v > b0) { b1 = b0; i1 = i0; b0 = v; i0 = e; }
            else if (v > b1) { b1 = v; i1 = e; }
        }
        float s  = expf(b1 - b0);
        float w0 = 1.f / (1.f + s);
        float w1v = s / (1.f + s);
        int p0 = atomicAdd(&g_cnt[i0], 1);
        int r0 = i0 * CAP + p0;
        g_tok[r0] = warp; g_rw[r0] = w0; g_slot_row[warp * 2 + 0] = r0;
        int p1 = atomicAdd(&g_cnt[i1], 1);
        int r1 = i1 * CAP + p1;
        g_tok[r1] = warp; g_rw[r1] = w1v; g_slot_row[warp * 2 + 1] = r1;
    }
}

__device__ __forceinline__ float gelu_exact(float v) {
    return 0.5f * v * (1.0f + erff(v * 0.70710678118654752f));
}

__device__ __forceinline__ void mma_f16(float c[4],
                                        uint32_t a0, uint32_t a1, uint32_t a2, uint32_t a3,
                                        uint32_t b0, uint32_t b1) {
    asm volatile(
        "mma.sync.aligned.m16n8k16.row.col.f32.f16.f16.f32 "
        "{%0,%1,%2,%3},{%4,%5,%6,%7},{%8,%9},{%0,%1,%2,%3};"
        : "+f"(c[0]), "+f"(c[1]), "+f"(c[2]), "+f"(c[3])
        : "r"(a0), "r"(a1), "r"(a2), "r"(a3), "r"(b0), "r"(b1));
}
__device__ __forceinline__ void ldm_x4(uint32_t& r0, uint32_t& r1, uint32_t& r2, uint32_t& r3,
                                       uint32_t addr) {
    asm volatile("ldmatrix.sync.aligned.m8n8.x4.shared.b16 {%0,%1,%2,%3}, [%4];"
        : "=r"(r0), "=r"(r1), "=r"(r2), "=r"(r3) : "r"(addr));
}
__device__ __forceinline__ void ldm_x4t(uint32_t& r0, uint32_t& r1, uint32_t& r2, uint32_t& r3,
                                        uint32_t addr) {
    asm volatile("ldmatrix.sync.aligned.m8n8.x4.trans.shared.b16 {%0,%1,%2,%3}, [%4];"
        : "=r"(r0), "=r"(r1), "=r"(r2), "=r"(r3) : "r"(addr));
}

#define CP_ASYNC16(dst, src) \
    asm volatile("cp.async.cg.shared.global [%0], [%1], 16;" :: "r"(dst), "l"(src))
#define CP_COMMIT() asm volatile("cp.async.commit_group;")
#define CP_WAIT1()  asm volatile("cp.async.wait_group 1;")
#define CP_WAIT0()  asm volatile("cp.async.wait_group 0;")

// ---------------------------------------------------------------
// fp16 MMA FFN GEMM — R10 inner loop, both modes now split-K with fp32 partials.
// MODE 0: g_h1s[spl] = g_xh[gather] @ w1h[kslice]   KSTR=768,  KLEN=384,  ND=3072, NSPL=2
// MODE 1: g_ys[spl]  = g_hh @ w2h[kslice]           KSTR=3072, KLEN=1024, ND=768,  NSPL=3
// 128x128 tile, BK=32 f16, 3 stages, depth-2, 1 barrier/iter, 8 warps (2x4), warp 64x32.
template<int KSTR, int KLEN, int ND, int MODE, int NSPL>
__global__ void __launch_bounds__(256, 2)
moe_mma_kernel() {
    const int e   = blockIdx.z / NSPL;
    const int spl = blockIdx.z % NSPL;
    const int cnt = g_cnt[e];
    const int m0  = blockIdx.y * 128;
    if (m0 >= cnt) return;
    const int n0   = blockIdx.x * 128;
    const int kbeg = spl * KLEN;

    extern __shared__ char smem[];
    const uint32_t sb = (uint32_t)__cvta_generic_to_shared(smem);

    const int t    = threadIdx.x;
    const int warp = t >> 5, lane = t & 31;
    const int wr = warp >> 2, wc = warp & 3;
    const int g  = lane >> 2, tg = lane & 3;

    // ---- A loader: thread t -> row t>>1, word chunks (t&1)*8 + {0,4} ----
    const int am = t >> 1;
    const int ac = (t & 1) * 8;
    const uint32_t* arow;
    if (MODE == 0) {
        int tok = (m0 + am < cnt) ? g_tok[e * CAP + m0 + am] : 0;
        arow = g_xh + (size_t)tok * (KSTR/2) + (kbeg/2);
    } else {
        int rr = e * CAP + ((m0 + am < cnt) ? m0 + am : 0);
        arow = g_hh + (size_t)rr * (KSTR/2) + (kbeg/2);
    }
    const uint32_t dA = sb + am * 80 + ac * 4;

    // ---- B loader: thread t -> k-row t>>3 (0..31), half col (t&7)*16 ----
    const int bk = t >> 3;
    const int bc = (t & 7) * 16;
    const __half* wh = (MODE == 0) ? g_w1h : g_w2h;
    const __half* bptr = wh + ((size_t)e * KSTR + kbeg + bk) * ND + n0 + bc;
    const uint32_t dB = sb + SB_B + bk * 272 + bc * 2;

#define LOAD_STAGE(s, it2)                                             \
    do {                                                               \
        const uint32_t* asrc = arow + (size_t)(it2) * 16 + ac;         \
        CP_ASYNC16(dA + (s) * ASTG, asrc);                             \
        CP_ASYNC16(dA + (s) * ASTG + 16, asrc + 4);                    \
        const __half* bsrc = bptr + (size_t)(it2) * 32 * ND;           \
        CP_ASYNC16(dB + (s) * BSTG, bsrc);                             \
        CP_ASYNC16(dB + (s) * BSTG + 16, bsrc + 8);                    \
        CP_COMMIT();                                                   \
    } while (0)

    // ---- fragment ldmatrix base addresses ----
    const uint32_t aFrag = sb + (wr * 64 + (lane & 15)) * 80 + (lane >> 4) * 16;
    const uint32_t bFrag = sb + SB_B + (lane & 15) * 272 + wc * 64 + (lane >> 4) * 16;

    float acc[4][4][4];
#pragma unroll
    for (int mt = 0; mt < 4; mt++)
#pragma unroll
        for (int nt = 0; nt < 4; nt++)
#pragma unroll
            for (int i = 0; i < 4; i++) acc[mt][nt][i] = 0.f;

    const int NIT = KLEN / 32;   // 12 or 32
    LOAD_STAGE(0, 0);
    LOAD_STAGE(1, 1);

    int s = 0;
    for (int it = 0; it < NIT; it++) {
        if (it + 1 < NIT) CP_WAIT1(); else CP_WAIT0();
        __syncthreads();
        if (it + 2 < NIT) {
            int sn = s + 2; if (sn >= NSTG) sn -= NSTG;
            LOAD_STAGE(sn, it + 2);
        }

#pragma unroll
        for (int kk = 0; kk < 2; kk++) {
            uint32_t af[4][4];
#pragma unroll
            for (int mt = 0; mt < 4; mt++)
                ldm_x4(af[mt][0], af[mt][1], af[mt][2], af[mt][3],
                       aFrag + s * ASTG + kk * 32 + mt * 1280);
            uint32_t bf[2][4];
#pragma unroll
            for (int ntp = 0; ntp < 2; ntp++)
                ldm_x4t(bf[ntp][0], bf[ntp][1], bf[ntp][2], bf[ntp][3],
                        bFrag + s * BSTG + kk * 4352 + ntp * 32);
#pragma unroll
            for (int mt = 0; mt < 4; mt++)
#pragma unroll
                for (int nt = 0; nt < 4; nt++)
                    mma_f16(acc[mt][nt], af[mt][0], af[mt][1], af[mt][2], af[mt][3],
                            bf[nt >> 1][(nt & 1) * 2], bf[nt >> 1][(nt & 1) * 2 + 1]);
        }
        s++; if (s >= NSTG) s -= NSTG;
    }
#undef LOAD_STAGE

    // ---- epilogue: plain fp32 partial store (both modes) ----
    float* ybase = (MODE == 0) ? &g_h1s[0][0] + (size_t)spl * ROWS * ND
                               : &g_ys[0][0]  + (size_t)spl * ROWS * ND;
#pragma unroll
    for (int mt = 0; mt < 4; mt++) {
        int rloc0 = m0 + wr * 64 + mt * 16 + g;
        int rloc1 = rloc0 + 8;
#pragma unroll
        for (int nt = 0; nt < 4; nt++) {
            int cc = n0 + wc * 32 + nt * 8 + tg * 2;
            if (rloc0 < cnt) {
                float* p = ybase + (size_t)(e * CAP + rloc0) * ND + cc;
                p[0] = acc[mt][nt][0];
                p[1] = acc[mt][nt][1];
            }
            if (rloc1 < cnt) {
                float* p = ybase + (size_t)(e * CAP + rloc1) * ND + cc;
                p[0] = acc[mt][nt][2];
                p[1] = acc[mt][nt][3];
            }
        }
    }
}

// ---------------------------------------------------------------
// gelu(sum of GEMM1 partials) -> packed half2 rows of g_hh
__global__ void gelupack_kernel() {
    const int row = blockIdx.x;              // 0..ROWS-1
    const int e = row >> 10;                 // /CAP
    const int m = row & (CAP - 1);
    if (m >= g_cnt[e]) return;
    const float2* p0 = (const float2*)(&g_h1s[0][0] + (size_t)row * F);
    const float2* p1 = (const float2*)(&g_h1s[1][0] + (size_t)row * F);
    uint32_t* dst = g_hh + (size_t)row * (F/2);
    for (int c = threadIdx.x; c < F/2; c += 256) {
        float2 a = p0[c];
        float2 b = p1[c];
        dst[c] = pack_h2(gelu_exact(a.x + b.x), gelu_exact(a.y + b.y));
    }
}

// ---------------------------------------------------------------
__global__ void combine_kernel(float* __restrict__ out) {
    int idx = blockIdx.x * blockDim.x + threadIdx.x;
    if (idx >= NTOK * H / 4) return;
    int elem = idx * 4;
    int n = elem / H;
    int h = elem % H;
    int r0 = g_slot_row[2 * n + 0];
    int r1 = g_slot_row[2 * n + 1];
    float gw0 = g_rw[r0], gw1 = g_rw[r1];

    float4 s0 = make_float4(0.f, 0.f, 0.f, 0.f);
    float4 s1 = make_float4(0.f, 0.f, 0.f, 0.f);
#pragma unroll
    for (int s = 0; s < NSPLIT; s++) {
        float4 a = *(const float4*)(&g_ys[s][0] + (size_t)r0 * H + h);
        float4 b = *(const float4*)(&g_ys[s][0] + (size_t)r1 * H + h);
        s0.x += a.x; s0.y += a.y; s0.z += a.z; s0.w += a.w;
        s1.x += b.x; s1.y += b.y; s1.z += b.z; s1.w += b.w;
    }
    float4 o;
    o.x = gw0 * s0.x + gw1 * s1.x;
    o.y = gw0 * s0.y + gw1 * s1.y;
    o.z = gw0 * s0.z + gw1 * s1.z;
    o.w = gw0 * s0.w + gw1 * s1.w;
    *(float4*)(out + elem) = o;
}

// ---------------------------------------------------------------
extern "C" void kernel_launch(void* const* d_in, const int* in_sizes, int n_in,
                              void* d_out, int out_size) {
    const float* x  = (const float*)d_in[0];
    const float* rw = (const float*)d_in[1];
    const float* w1 = (const float*)d_in[2];
    const float* w2 = (const float*)d_in[3];
    float* out = (float*)d_out;

    cudaFuncSetAttribute(moe_mma_kernel<H, KSPL1, F, 0, NSPL1>,
                         cudaFuncAttributeMaxDynamicSharedMemorySize, SMEM_BYTES);
    cudaFuncSetAttribute(moe_mma_kernel<F, KSPL, H, 1, NSPLIT>,
                         cudaFuncAttributeMaxDynamicSharedMemorySize, SMEM_BYTES);

    zero_cnt_kernel<<<1, 32>>>();
    router_kernel<<<NTOK / 8, 256>>>(x, rw);

    size_t wtot = ((size_t)E * H * F + (size_t)E * F * H) / 8;
    convert_w_kernel<<<(unsigned)((wtot + 255) / 256), 256>>>(w1, w2);

    dim3 g1(F / 128, NTOK / 128, E * NSPL1);         // (24, 8, 16)
    moe_mma_kernel<H, KSPL1, F, 0, NSPL1><<<g1, 256, SMEM_BYTES>>>();

    gelupack_kernel<<<ROWS, 256>>>();

    dim3 g2(H / 128, NTOK / 128, E * NSPLIT);        // (6, 8, 24)
    moe_mma_kernel<F, KSPL, H, 1, NSPLIT><<<g2, 256, SMEM_BYTES>>>();

    combine_kernel<<<(NTOK * H / 4 + 255) / 256, 256>>>(out);
}

// round 15
// speedup vs baseline: 1.5102x; 1.0040x over previous
#include <cuda_runtime.h>
#include <cuda_fp16.h>
#include <math.h>
#include <stdint.h>

#define H    768
#define F    3072
#define E    8
#define NTOK 1024
#define CAP  1024
#define ROWS (E*CAP)
#define NSPLIT 3            // GEMM2 K-split
#define KSPL (F / NSPLIT)   // 1024

#define NSTG 3
// smem stage sizes (bytes)
#define ASTG 10240          // 128 rows x 80B (16 words used + 4 pad)
#define BSTG 8704           // 32 k-rows x 272B (128 halfs + 8 pad)
#define SB_B (NSTG*ASTG)
#define SMEM_BYTES (NSTG*(ASTG+BSTG))   // 56832

// ---- scratch (static device globals; no runtime allocation) ----
__device__ int      g_cnt[E];
__device__ int      g_tok[ROWS];
__device__ float    g_rw[ROWS];
__device__ int      g_slot_row[NTOK*2];
__device__ uint32_t g_xh[NTOK*(H/2)];            // x packed half2 along k
__device__ uint32_t g_hh[(size_t)ROWS*(F/2)];    // gelu(x@w1) packed half2 along k
__device__ __half   g_w1h[(size_t)E*H*F];        // w1 plain half [e][k][n]
__device__ __half   g_w2h[(size_t)E*F*H];        // w2 plain half [e][k][n]
__device__ float    g_ys[NSPLIT][(size_t)ROWS * H];

// ---------------------------------------------------------------
__device__ __forceinline__ uint32_t pack_h2(float a, float b) {
    __half2 h = __floats2half2_rn(a, b);
    return *(uint32_t*)&h;
}

__global__ void zero_cnt_kernel() {
    if (threadIdx.x < E) g_cnt[threadIdx.x] = 0;
}

// linear fp32 -> fp16 stream for both weights (layout preserved)
__global__ void convert_w_kernel(const float* __restrict__ w1,
                                 const float* __restrict__ w2) {
    size_t i = (size_t)blockIdx.x * blockDim.x + threadIdx.x;   // 8 elems each
    const size_t n1 = (size_t)E * H * F / 8;
    const size_t n2 = (size_t)E * F * H / 8;
    const float* src;
    __half* dst;
    size_t j;
    if (i < n1)           { src = w1; dst = g_w1h; j = i; }
    else if (i < n1 + n2) { src = w2; dst = g_w2h; j = i - n1; }
    else return;
    float4 a = ((const float4*)src)[2*j];
    float4 b = ((const float4*)src)[2*j+1];
    uint4 o;
    o.x = pack_h2(a.x, a.y); o.y = pack_h2(a.z, a.w);
    o.z = pack_h2(b.x, b.y); o.w = pack_h2(b.z, b.w);
    ((uint4*)dst)[j] = o;
}

// router + x fp16 packing fused (1 warp per token)
__global__ void router_kernel(const float* __restrict__ x,
                              const float* __restrict__ rw) {
    int warp = (blockIdx.x * blockDim.x + threadIdx.x) >> 5;
    int lane = threadIdx.x & 31;
    if (warp >= NTOK) return;
    const float* xr = x + warp * H;
    {
        const float4* src = (const float4*)xr;
        uint32_t* dst = g_xh + warp * (H/2);
#pragma unroll
        for (int i = lane; i < H / 4; i += 32) {
            float4 v = src[i];
            dst[2*i]   = pack_h2(v.x, v.y);
            dst[2*i+1] = pack_h2(v.z, v.w);
        }
    }
    float acc[E];
#pragma unroll
    for (int e = 0; e < E; e++) acc[e] = 0.f;
    for (int k = lane; k < H; k += 32) {
        float xv = xr[k];
        const float* r = rw + k * E;
#pragma unroll
        for (int e = 0; e < E; e++) acc[e] += xv * r[e];
    }
#pragma unroll
    for (int e = 0; e < E; e++) {
#pragma unroll
        for (int o = 16; o > 0; o >>= 1)
            acc[e] += __shfl_down_sync(0xffffffffu, acc[e], o);
    }
    if (lane == 0) {
        float b0 = -INFINITY, b1 = -INFINITY;
        int i0 = 0, i1 = 0;
#pragma unroll
        for (int e = 0; e < E; e++) {
            float v = acc[e];
            if (v > b0) { b1 = b0; i1 = i0; b0 = v; i0 = e; }
            else if (v > b1) { b1 = v; i1 = e; }
        }
        float s  = expf(b1 - b0);
        float w0 = 1.f / (1.f + s);
        float w1v = s / (1.f + s);
        int p0 = atomicAdd(&g_cnt[i0], 1);
        int r0 = i0 * CAP + p0;
        g_tok[r0] = warp; g_rw[r0] = w0; g_slot_row[warp * 2 + 0] = r0;
        int p1 = atomicAdd(&g_cnt[i1], 1);
        int r1 = i1 * CAP + p1;
        g_tok[r1] = warp; g_rw[r1] = w1v; g_slot_row[warp * 2 + 1] = r1;
    }
}

__device__ __forceinline__ float gelu_exact(float v) {
    return 0.5f * v * (1.0f + erff(v * 0.70710678118654752f));
}

__device__ __forceinline__ void mma_f16(float c[4],
                                        uint32_t a0, uint32_t a1, uint32_t a2, uint32_t a3,
                                        uint32_t b0, uint32_t b1) {
    asm volatile(
        "mma.sync.aligned.m16n8k16.row.col.f32.f16.f16.f32 "
        "{%0,%1,%2,%3},{%4,%5,%6,%7},{%8,%9},{%0,%1,%2,%3};"
        : "+f"(c[0]), "+f"(c[1]), "+f"(c[2]), "+f"(c[3])
        : "r"(a0), "r"(a1), "r"(a2), "r"(a3), "r"(b0), "r"(b1));
}
__device__ __forceinline__ void ldm_x4(uint32_t& r0, uint32_t& r1, uint32_t& r2, uint32_t& r3,
                                       uint32_t addr) {
    asm volatile("ldmatrix.sync.aligned.m8n8.x4.shared.b16 {%0,%1,%2,%3}, [%4];"
        : "=r"(r0), "=r"(r1), "=r"(r2), "=r"(r3) : "r"(addr));
}
__device__ __forceinline__ void ldm_x4t(uint32_t& r0, uint32_t& r1, uint32_t& r2, uint32_t& r3,
                                        uint32_t addr) {
    asm volatile("ldmatrix.sync.aligned.m8n8.x4.trans.shared.b16 {%0,%1,%2,%3}, [%4];"
        : "=r"(r0), "=r"(r1), "=r"(r2), "=r"(r3) : "r"(addr));
}

#define CP_ASYNC16(dst, src) \
    asm volatile("cp.async.cg.shared.global [%0], [%1], 16;" :: "r"(dst), "l"(src))
#define CP_COMMIT() asm volatile("cp.async.commit_group;")
#define CP_WAIT1()  asm volatile("cp.async.wait_group 1;")
#define CP_WAIT0()  asm volatile("cp.async.wait_group 0;")

// ---------------------------------------------------------------
// fp16 MMA FFN GEMM — R10 inner loop.
// MODE 0: g_hh = h2(gelu(g_xh[gather] @ w1h))  KSTR=768, KLEN=768, ND=3072
//         grid (6, 8, E*4): x = n-subtile in 768-window, z = e*4 + window
//         (GEMM2-style locality: co-resident blocks share one expert-window)
// MODE 1: g_ys[spl] = g_hh @ w2h[kslice]       KSTR=3072, KLEN=1024, ND=768
//         grid (6, 8, E*NSPLIT)
// 128x128 tile, BK=32 f16, 3 stages, depth-2, 1 barrier/iter, 8 warps (2x4).
template<int KSTR, int KLEN, int ND, int MODE>
__global__ void __launch_bounds__(256, 2)
moe_mma_kernel() {
    int e, n0, kbeg;
    if (MODE == 0) {
        e    = blockIdx.z >> 2;
        n0   = (blockIdx.z & 3) * 768 + blockIdx.x * 128;
        kbeg = 0;
    } else {
        e    = blockIdx.z / NSPLIT;
        n0   = blockIdx.x * 128;
        kbeg = (blockIdx.z % NSPLIT) * KLEN;
    }
    const int cnt = g_cnt[e];
    const int m0  = blockIdx.y * 128;
    if (m0 >= cnt) return;

    extern __shared__ char smem[];
    const uint32_t sb = (uint32_t)__cvta_generic_to_shared(smem);

    const int t    = threadIdx.x;
    const int warp = t >> 5, lane = t & 31;
    const int wr = warp >> 2, wc = warp & 3;
    const int g  = lane >> 2, tg = lane & 3;

    // ---- A loader: thread t -> row t>>1, word chunks (t&1)*8 + {0,4} ----
    const int am = t >> 1;
    const int ac = (t & 1) * 8;
    const uint32_t* arow;
    if (MODE == 0) {
        int tok = (m0 + am < cnt) ? g_tok[e * CAP + m0 + am] : 0;
        arow = g_xh + (size_t)tok * (KSTR/2);
    } else {
        int rr = e * CAP + ((m0 + am < cnt) ? m0 + am : 0);
        arow = g_hh + (size_t)rr * (KSTR/2) + (kbeg/2);
    }
    const uint32_t dA = sb + am * 80 + ac * 4;

    // ---- B loader: thread t -> k-row t>>3 (0..31), half col (t&7)*16 ----
    const int bk = t >> 3;
    const int bc = (t & 7) * 16;
    const __half* wh = (MODE == 0) ? g_w1h : g_w2h;
    const __half* bptr = wh + ((size_t)e * KSTR + kbeg + bk) * ND + n0 + bc;
    const uint32_t dB = sb + SB_B + bk * 272 + bc * 2;

#define LOAD_STAGE(s, it2)                                             \
    do {                                                               \
        const uint32_t* asrc = arow + (size_t)(it2) * 16 + ac;         \
        CP_ASYNC16(dA + (s) * ASTG, asrc);                             \
        CP_ASYNC16(dA + (s) * ASTG + 16, asrc + 4);                    \
        const __half* bsrc = bptr + (size_t)(it2) * 32 * ND;           \
        CP_ASYNC16(dB + (s) * BSTG, bsrc);                             \
        CP_ASYNC16(dB + (s) * BSTG + 16, bsrc + 8);                    \
        CP_COMMIT();                                                   \
    } while (0)

    // ---- fragment ldmatrix base addresses ----
    const uint32_t aFrag = sb + (wr * 64 + (lane & 15)) * 80 + (lane >> 4) * 16;
    const uint32_t bFrag = sb + SB_B + (lane & 15) * 272 + wc * 64 + (lane >> 4) * 16;

    float acc[4][4][4];
#pragma unroll
    for (int mt = 0; mt < 4; mt++)
#pragma unroll
        for (int nt = 0; nt < 4; nt++)
#pragma unroll
            for (int i = 0; i < 4; i++) acc[mt][nt][i] = 0.f;

    const int NIT = KLEN / 32;   // 24 or 32
    LOAD_STAGE(0, 0);
    LOAD_STAGE(1, 1);

    int s = 0;
    for (int it = 0; it < NIT; it++) {
        if (it + 1 < NIT) CP_WAIT1(); else CP_WAIT0();
        __syncthreads();
        if (it + 2 < NIT) {
            int sn = s + 2; if (sn >= NSTG) sn -= NSTG;
            LOAD_STAGE(sn, it + 2);
        }

#pragma unroll
        for (int kk = 0; kk < 2; kk++) {
            uint32_t af[4][4];
#pragma unroll
            for (int mt = 0; mt < 4; mt++)
                ldm_x4(af[mt][0], af[mt][1], af[mt][2], af[mt][3],
                       aFrag + s * ASTG + kk * 32 + mt * 1280);
            uint32_t bf[2][4];
#pragma unroll
            for (int ntp = 0; ntp < 2; ntp++)
                ldm_x4t(bf[ntp][0], bf[ntp][1], bf[ntp][2], bf[ntp][3],
                        bFrag + s * BSTG + kk * 4352 + ntp * 32);
#pragma unroll
            for (int mt = 0; mt < 4; mt++)
#pragma unroll
                for (int nt = 0; nt < 4; nt++)
                    mma_f16(acc[mt][nt], af[mt][0], af[mt][1], af[mt][2], af[mt][3],
                            bf[nt >> 1][(nt & 1) * 2], bf[nt >> 1][(nt & 1) * 2 + 1]);
        }
        s++; if (s >= NSTG) s -= NSTG;
    }
#undef LOAD_STAGE

    // ---- epilogue ----
#pragma unroll
    for (int mt = 0; mt < 4; mt++) {
        int rloc0 = m0 + wr * 64 + mt * 16 + g;
        int rloc1 = rloc0 + 8;
#pragma unroll
        for (int nt = 0; nt < 4; nt++) {
            if (MODE == 0) {
                int pc = (n0 >> 1) + wc * 16 + nt * 4 + tg;   // packed half2 col
                if (rloc0 < cnt)
                    g_hh[(size_t)(e * CAP + rloc0) * (ND/2) + pc] =
                        pack_h2(gelu_exact(acc[mt][nt][0]), gelu_exact(acc[mt][nt][1]));
                if (rloc1 < cnt)
                    g_hh[(size_t)(e * CAP + rloc1) * (ND/2) + pc] =
                        pack_h2(gelu_exact(acc[mt][nt][2]), gelu_exact(acc[mt][nt][3]));
            } else {
                int spl = blockIdx.z % NSPLIT;
                int cc = n0 + wc * 32 + nt * 8 + tg * 2;
                if (rloc0 < cnt) {
                    float* p = &g_ys[spl][(size_t)(e * CAP + rloc0) * ND + cc];
                    p[0] = acc[mt][nt][0];
                    p[1] = acc[mt][nt][1];
                }
                if (rloc1 < cnt) {
                    float* p = &g_ys[spl][(size_t)(e * CAP + rloc1) * ND + cc];
                    p[0] = acc[mt][nt][2];
                    p[1] = acc[mt][nt][3];
                }
            }
        }
    }
}

// ---------------------------------------------------------------
__global__ void combine_kernel(float* __restrict__ out) {
    int idx = blockIdx.x * blockDim.x + threadIdx.x;
    if (idx >= NTOK * H / 4) return;
    int elem = idx * 4;
    int n = elem / H;
    int h = elem % H;
    int r0 = g_slot_row[2 * n + 0];
    int r1 = g_slot_row[2 * n + 1];
    float gw0 = g_rw[r0], gw1 = g_rw[r1];

    float4 s0 = make_float4(0.f, 0.f, 0.f, 0.f);
    float4 s1 = make_float4(0.f, 0.f, 0.f, 0.f);
#pragma unroll
    for (int s = 0; s < NSPLIT; s++) {
        float4 a = *(const float4*)(&g_ys[s][0] + (size_t)r0 * H + h);
        float4 b = *(const float4*)(&g_ys[s][0] + (size_t)r1 * H + h);
        s0.x += a.x; s0.y += a.y; s0.z += a.z; s0.w += a.w;
        s1.x += b.x; s1.y += b.y; s1.z += b.z; s1.w += b.w;
    }
    float4 o;
    o.x = gw0 * s0.x + gw1 * s1.x;
    o.y = gw0 * s0.y + gw1 * s1.y;
    o.z = gw0 * s0.z + gw1 * s1.z;
    o.w = gw0 * s0.w + gw1 * s1.w;
    *(float4*)(out + elem) = o;
}

// ---------------------------------------------------------------
extern "C" void kernel_launch(void* const* d_in, const int* in_sizes, int n_in,
                              void* d_out, int out_size) {
    const float* x  = (const float*)d_in[0];
    const float* rw = (const float*)d_in[1];
    const float* w1 = (const float*)d_in[2];
    const float* w2 = (const float*)d_in[3];
    float* out = (float*)d_out;

    cudaFuncSetAttribute(moe_mma_kernel<H, H, F, 0>,
                         cudaFuncAttributeMaxDynamicSharedMemorySize, SMEM_BYTES);
    cudaFuncSetAttribute(moe_mma_kernel<F, KSPL, H, 1>,
                         cudaFuncAttributeMaxDynamicSharedMemorySize, SMEM_BYTES);

    zero_cnt_kernel<<<1, 32>>>();
    router_kernel<<<NTOK / 8, 256>>>(x, rw);

    size_t wtot = ((size_t)E * H * F + (size_t)E * F * H) / 8;
    convert_w_kernel<<<(unsigned)((wtot + 255) / 256), 256>>>(w1, w2);

    dim3 g1(6, NTOK / 128, E * 4);                   // (6, 8, 32) — GEMM2-style
    moe_mma_kernel<H, H, F, 0><<<g1, 256, SMEM_BYTES>>>();

    dim3 g2(H / 128, NTOK / 128, E * NSPLIT);        // (6, 8, 24)
    moe_mma_kernel<F, KSPL, H, 1><<<g2, 256, SMEM_BYTES>>>();

    combine_kernel<<<(NTOK * H / 4 + 255) / 256, 256>>>(out);
}